// round 11
// baseline (speedup 1.0000x reference)
#include <cuda_runtime.h>
#include <math.h>

#define NTOK   49
#define DIMC   192
#define HEADS  6
#define HDIM   32
#define NWMASK 64
#define QSCALE 0.17677669529663687f
#define NTHREADS 512
#define NCTAS   1024
#define WPC     4
#define NWIN    4096
#define GROWS   (NWIN * NTOK)              // 200704 = 1568 * 128

#define XS_STRIDE  196
#define QKV_STRIDE 196
#define VT_STRIDE  60
#define ATT_STRIDE 60
#define VT_GSTRIDE 52                      // gmem v^T row stride (words)

// ---- main kernel smem layout (words) ----
#define OFF_QS 17640                       // region0 [0,17640) = att probs
#define OFF_KS 27244
#define OFF_VT 36848
#define SMEM_WORDS (36848 + 192 * 60)      // 48368 words = 193,472 B

// ---- GEMM kernel smem: xs 128 x 196 ----
#define GSMEM_WORDS (128 * 196)            // 25088 words = 100,352 B

// ---- precomputed / intermediate device globals ----
__device__ uint2 g_wfrag1[8 * 24 * 9 * 32];        // q-cols pre-scaled by QSCALE
__device__ uint2 g_wfrag3[8 * 24 * 3 * 32];
__device__ float g_bq[576];                         // bias, q-part pre-scaled
__device__ float g_cmb[NWMASK * HEADS * NTOK * 56]; // bias+mask combined
__device__ unsigned g_q[(size_t)GROWS * DIMC];      // q tf32 bits (scaled)
__device__ unsigned g_k[(size_t)GROWS * DIMC];      // k tf32 bits
__device__ unsigned g_vt[(size_t)NWIN * DIMC * VT_GSTRIDE]; // v^T tf32 bits (pad cols zero)

__device__ __forceinline__ unsigned cvt_tf32(float f) {
    unsigned r;
    asm("cvt.rna.tf32.f32 %0, %1;" : "=r"(r) : "f"(f));
    return r;
}

__device__ __forceinline__ void mma_tf32(float* d, const unsigned* a, const unsigned* bb) {
    asm volatile(
        "mma.sync.aligned.m16n8k8.row.col.f32.tf32.tf32.f32 "
        "{%0,%1,%2,%3}, {%4,%5,%6,%7}, {%8,%9}, {%0,%1,%2,%3};"
        : "+f"(d[0]), "+f"(d[1]), "+f"(d[2]), "+f"(d[3])
        : "r"(a[0]), "r"(a[1]), "r"(a[2]), "r"(a[3]),
          "r"(bb[0]), "r"(bb[1]));
}

__device__ __forceinline__ void ldsm4(unsigned* r, unsigned addr) {
    asm volatile("ldmatrix.sync.aligned.m8n8.x4.shared.b16 {%0,%1,%2,%3}, [%4];"
                 : "=r"(r[0]), "=r"(r[1]), "=r"(r[2]), "=r"(r[3]) : "r"(addr));
}

__device__ __forceinline__ void ldsm2(unsigned* r, unsigned addr) {
    asm volatile("ldmatrix.sync.aligned.m8n8.x2.shared.b16 {%0,%1}, [%2];"
                 : "=r"(r[0]), "=r"(r[1]) : "r"(addr));
}

__global__ void prep_kernel(const float* __restrict__ w_qkv,
                            const float* __restrict__ w_proj,
                            const float* __restrict__ table,
                            const float* __restrict__ mask,
                            const float* __restrict__ b_qkv)
{
    const int stride = gridDim.x * blockDim.x;
    const int tid0 = blockIdx.x * blockDim.x + threadIdx.x;

    for (int i = tid0; i < 8 * 24 * 9 * 32; i += stride) {
        int lane = i & 31;
        int t    = (i >> 5) % 9;
        int k8   = (i / 288) % 24;
        int ns   = i / 6912;
        int lr = lane & 3, lg = lane >> 2;
        int col = ns * 72 + t * 8 + lg;
        int k0  = k8 * 8 + lr;
        float sc = (col < DIMC) ? QSCALE : 1.0f;
        g_wfrag1[i] = make_uint2(cvt_tf32(w_qkv[k0 * 576 + col] * sc),
                                 cvt_tf32(w_qkv[(k0 + 4) * 576 + col] * sc));
    }
    for (int i = tid0; i < 8 * 24 * 3 * 32; i += stride) {
        int lane = i & 31;
        int t    = (i >> 5) % 3;
        int k8   = (i / 96) % 24;
        int ns   = i / 2304;
        int lr = lane & 3, lg = lane >> 2;
        int col = ns * 24 + t * 8 + lg;
        int k0  = k8 * 8 + lr;
        g_wfrag3[i] = make_uint2(cvt_tf32(w_proj[k0 * 192 + col]),
                                 cvt_tf32(w_proj[(k0 + 4) * 192 + col]));
    }
    for (int i = tid0; i < 576; i += stride)
        g_bq[i] = b_qkv[i] * (i < DIMC ? QSCALE : 1.0f);

    for (int i = tid0; i < NWMASK * HEADS * NTOK * NTOK; i += stride) {
        int wm = i / (HEADS * NTOK * NTOK);
        int r  = i % (HEADS * NTOK * NTOK);
        int h  = r / (NTOK * NTOK);
        int r2 = r % (NTOK * NTOK);
        int p = r2 / NTOK, q = r2 % NTOK;
        int ip = p / 7, jp = p % 7, iq = q / 7, jq = q % 7;
        int ridx = (jp - jq + 6) * 13 + (ip - iq + 6);
        g_cmb[((wm * HEADS + h) * NTOK + p) * 56 + q] =
            mask[wm * (NTOK * NTOK) + p * NTOK + q] + table[ridx * HEADS + h];
    }
}

// ============ kernel 1: QKV GEMM over flattened tokens (M=200704) ============
// CTA: 512 thr, tile M=128 x N=576, warp = 64 rows x 72 cols, K=192.
__global__ __launch_bounds__(NTHREADS, 1)
void qkv_gemm_kernel(const float* __restrict__ x)
{
    extern __shared__ unsigned smu[];
    unsigned* xsu = smu;                   // 128 x 196 tf32 bits

    const unsigned sbase = (unsigned)__cvta_generic_to_shared(smu);
    const int tid  = threadIdx.x;
    const int lane = tid & 31;
    const int w    = tid >> 5;
    const int lg   = lane >> 2;
    const int lr   = lane & 3;
    const int lrow = (lane & 7) + ((lane >> 3) & 1) * 8;
    const int lcol = (lane >> 4) * 4;
    const int mb   = blockIdx.x;           // 0..1567

    // load x block 128 x 192 (6144 float4), cvt to tf32 bits
    {
        const float4* xg4 = (const float4*)(x + (size_t)mb * 128 * DIMC);
        #pragma unroll
        for (int j = 0; j < 12; j++) {
            int idx = tid + j * NTHREADS;
            float4 v = xg4[idx];
            int row = idx / 48, c4 = idx % 48;
            *(uint4*)&xsu[row * XS_STRIDE + c4 * 4] =
                make_uint4(cvt_tf32(v.x), cvt_tf32(v.y), cvt_tf32(v.z), cvt_tf32(v.w));
        }
    }
    __syncthreads();

    const int ns = w >> 1;
    const int mq = (w & 1) * 64;
    const uint2* gw = g_wfrag1 + ns * 6912 + lane;

    float d[4][9][4];
    #pragma unroll
    for (int s = 0; s < 4; s++)
        #pragma unroll
        for (int t = 0; t < 9; t++)
            #pragma unroll
            for (int j = 0; j < 4; j++) d[s][t][j] = 0.0f;

    const unsigned abase = sbase + (((mq + lrow) * XS_STRIDE + lcol) << 2);
    #pragma unroll 2
    for (int k8 = 0; k8 < 24; ++k8) {
        uint2 bbv[9];
        #pragma unroll
        for (int t = 0; t < 9; t++) bbv[t] = gw[(k8 * 9 + t) * 32];

        unsigned a[4][4];
        #pragma unroll
        for (int s = 0; s < 4; s++)
            ldsm4(a[s], abase + ((s * 16 * XS_STRIDE + k8 * 8) << 2));
        #pragma unroll
        for (int t = 0; t < 9; t++)
            #pragma unroll
            for (int s = 0; s < 4; s++)
                mma_tf32(d[s][t], a[s], (const unsigned*)&bbv[t]);
    }

    // epilogue: +bias (q pre-scaled), write q/k natural, v transposed per window
    #pragma unroll
    for (int s = 0; s < 4; s++) {
        int r0 = mb * 128 + mq + s * 16 + lg;
        int r1 = r0 + 8;
        int win0 = r0 / NTOK, tok0 = r0 - win0 * NTOK;
        int win1 = r1 / NTOK, tok1 = r1 - win1 * NTOK;
        #pragma unroll
        for (int t = 0; t < 9; t++) {
            int col  = ns * 72 + t * 8 + 2 * lr;
            int part = col / DIMC;
            int cc   = col % DIMC;
            float2 bq = *(const float2*)&g_bq[col];
            unsigned v00 = cvt_tf32(d[s][t][0] + bq.x);
            unsigned v01 = cvt_tf32(d[s][t][1] + bq.y);
            unsigned v10 = cvt_tf32(d[s][t][2] + bq.x);
            unsigned v11 = cvt_tf32(d[s][t][3] + bq.y);
            if (part == 0) {
                *(uint2*)&g_q[(size_t)r0 * DIMC + cc] = make_uint2(v00, v01);
                *(uint2*)&g_q[(size_t)r1 * DIMC + cc] = make_uint2(v10, v11);
            } else if (part == 1) {
                *(uint2*)&g_k[(size_t)r0 * DIMC + cc] = make_uint2(v00, v01);
                *(uint2*)&g_k[(size_t)r1 * DIMC + cc] = make_uint2(v10, v11);
            } else {
                g_vt[(size_t)(win0 * DIMC + cc)     * VT_GSTRIDE + tok0] = v00;
                g_vt[(size_t)(win0 * DIMC + cc + 1) * VT_GSTRIDE + tok0] = v01;
                g_vt[(size_t)(win1 * DIMC + cc)     * VT_GSTRIDE + tok1] = v10;
                g_vt[(size_t)(win1 * DIMC + cc + 1) * VT_GSTRIDE + tok1] = v11;
            }
        }
    }
}

// ============ kernel 2: attention + proj (phases 2-3, unchanged math) ============
__global__ __launch_bounds__(NTHREADS, 1)
void winattn_kernel(const float* __restrict__ b_proj, float* __restrict__ out)
{
    extern __shared__ unsigned smu[];

    unsigned* attu = smu;                  // 6x49x60 prob bits (region0)
    unsigned* qsu  = smu + OFF_QS;         // q bits, later O bits
    unsigned* ksu  = smu + OFF_KS;
    unsigned* vtu  = smu + OFF_VT;

    const unsigned sbase = (unsigned)__cvta_generic_to_shared(smu);

    const int tid  = threadIdx.x;
    const int lane = tid & 31;
    const int w    = tid >> 5;
    const int lg   = lane >> 2;
    const int lr   = lane & 3;
    const int lrow = (lane & 7) + ((lane >> 3) & 1) * 8;
    const int lcol = (lane >> 4) * 4;
    const int brow8 = lane & 7;
    const int bcol  = ((lane >> 3) & 1) * 4;
    const int btsel = lane >> 4;

    // one-time: zero vt pad cols 52..55 (49..51 come zeroed from g_vt pad)
    for (int i = tid; i < DIMC * 4; i += NTHREADS)
        vtu[(i >> 2) * VT_STRIDE + 52 + (i & 3)] = 0u;

    for (int it = 0; it < WPC; ++it) {
        const int b = blockIdx.x * WPC + it;

        // ---- copy-in: q, k, v^T window blocks (register-staged, MLP=15) ----
        {
            const uint4* gq4 = (const uint4*)(g_q + (size_t)b * NTOK * DIMC);
            const uint4* gk4 = (const uint4*)(g_k + (size_t)b * NTOK * DIMC);
            const uint4* gv4 = (const uint4*)(g_vt + (size_t)b * DIMC * VT_GSTRIDE);
            uint4 rq[5], rk[5], rv[5];
            #pragma unroll
            for (int j = 0; j < 5; j++) {
                int idx = tid + j * NTHREADS;
                if (idx < 2352) { rq[j] = gq4[idx]; rk[j] = gk4[idx]; }
                if (idx < 2496) rv[j] = gv4[idx];
            }
            #pragma unroll
            for (int j = 0; j < 5; j++) {
                int idx = tid + j * NTHREADS;
                if (idx < 2352) {
                    int tok = idx / 48, c4 = idx % 48;
                    *(uint4*)&qsu[tok * QKV_STRIDE + c4 * 4] = rq[j];
                    *(uint4*)&ksu[tok * QKV_STRIDE + c4 * 4] = rk[j];
                }
                if (idx < 2496) {
                    int dd = idx / 13, c4 = idx % 13;
                    *(uint4*)&vtu[dd * VT_STRIDE + c4 * 4] = rv[j];
                }
            }
        }
        __syncthreads();

        // ====== phase 2: attention — 24 (head, m16-tile) units over 16 warps ======
        {
            const int wm = b & (NWMASK - 1);
            for (int ui = w; ui < 24; ui += 16) {
                const int h  = ui >> 2;
                const int m0 = (ui & 3) * 16;

                float2 cmb[2][7];
                #pragma unroll
                for (int half = 0; half < 2; half++) {
                    int p = m0 + lg + 8 * half;
                    int pc = (p < NTOK) ? p : (NTOK - 1);
                    const float2* crow =
                        (const float2*)&g_cmb[((wm * HEADS + h) * NTOK + pc) * 56];
                    #pragma unroll
                    for (int t = 0; t < 7; t++)
                        cmb[half][t] = crow[(t * 8 + 2 * lr) >> 1];
                }

                float d[7][4];
                #pragma unroll
                for (int t = 0; t < 7; t++)
                    #pragma unroll
                    for (int j = 0; j < 4; j++) d[t][j] = 0.0f;

                const unsigned qab = sbase +
                    ((OFF_QS + (m0 + lrow) * QKV_STRIDE + h * HDIM + lcol) << 2);
                const unsigned kB0 = sbase +
                    ((OFF_KS + (btsel * 8 + brow8) * QKV_STRIDE + h * HDIM + bcol) << 2);
                #pragma unroll
                for (int k8 = 0; k8 < 4; ++k8) {
                    unsigned a[4];
                    ldsm4(a, qab + (k8 * 8 << 2));
                    unsigned bb[14];
                    ldsm4(bb,      kB0 + ((0 * 8 * QKV_STRIDE + k8 * 8) << 2));
                    ldsm4(bb + 4,  kB0 + ((2 * 8 * QKV_STRIDE + k8 * 8) << 2));
                    ldsm4(bb + 8,  kB0 + ((4 * 8 * QKV_STRIDE + k8 * 8) << 2));
                    ldsm2(bb + 12, kB0 + ((6 * 8 * QKV_STRIDE + k8 * 8) << 2));
                    #pragma unroll
                    for (int t = 0; t < 7; t++)
                        mma_tf32(d[t], a, bb + 2 * t);
                }

                float inv2[2];
                #pragma unroll
                for (int half = 0; half < 2; half++) {
                    int p = m0 + lg + 8 * half;
                    float mx = -1e30f;
                    if (p < NTOK) {
                        #pragma unroll
                        for (int t = 0; t < 7; t++) {
                            int q0 = t * 8 + 2 * lr;
                            float v0 = -1e30f, v1 = -1e30f;
                            if (q0 < NTOK)     v0 = d[t][2 * half]     + cmb[half][t].x;
                            if (q0 + 1 < NTOK) v1 = d[t][2 * half + 1] + cmb[half][t].y;
                            d[t][2 * half]     = v0;
                            d[t][2 * half + 1] = v1;
                            mx = fmaxf(mx, fmaxf(v0, v1));
                        }
                    }
                    mx = fmaxf(mx, __shfl_xor_sync(0xffffffffu, mx, 1));
                    mx = fmaxf(mx, __shfl_xor_sync(0xffffffffu, mx, 2));
                    float sum = 0.0f;
                    if (p < NTOK) {
                        #pragma unroll
                        for (int t = 0; t < 7; t++) {
                            #pragma unroll
                            for (int c = 0; c < 2; c++) {
                                int q = t * 8 + 2 * lr + c;
                                float e = (q < NTOK) ? __expf(d[t][2 * half + c] - mx) : 0.0f;
                                d[t][2 * half + c] = e;
                                sum += e;
                            }
                        }
                        unsigned* arow = attu + (h * NTOK + p) * ATT_STRIDE;
                        #pragma unroll
                        for (int t = 0; t < 7; t++) {
                            int q0 = t * 8 + 2 * lr;
                            uint2 bits = make_uint2(0u, 0u);
                            if (q0 < NTOK)     bits.x = cvt_tf32(d[t][2 * half]);
                            if (q0 + 1 < NTOK) bits.y = cvt_tf32(d[t][2 * half + 1]);
                            *(uint2*)&arow[q0] = bits;
                        }
                    }
                    sum += __shfl_xor_sync(0xffffffffu, sum, 1);
                    sum += __shfl_xor_sync(0xffffffffu, sum, 2);
                    inv2[half] = 1.0f / sum;
                }
                __syncwarp();

                float o[4][4];
                #pragma unroll
                for (int t = 0; t < 4; t++)
                    #pragma unroll
                    for (int j = 0; j < 4; j++) o[t][j] = 0.0f;

                const unsigned aab = sbase +
                    (((h * NTOK + m0 + lrow) * ATT_STRIDE + lcol) << 2);
                const unsigned vB0 = sbase +
                    ((OFF_VT + (h * HDIM + btsel * 8 + brow8) * VT_STRIDE + bcol) << 2);
                #pragma unroll
                for (int k8 = 0; k8 < 7; ++k8) {
                    unsigned a[4];
                    ldsm4(a, aab + (k8 * 8 << 2));
                    unsigned bb[8];
                    ldsm4(bb,     vB0 + ((0 * 8 * VT_STRIDE + k8 * 8) << 2));
                    ldsm4(bb + 4, vB0 + ((2 * 8 * VT_STRIDE + k8 * 8) << 2));
                    #pragma unroll
                    for (int t = 0; t < 4; t++)
                        mma_tf32(o[t], a, bb + 2 * t);
                }
                int r0 = m0 + lg, r1 = r0 + 8;
                #pragma unroll
                for (int t = 0; t < 4; t++) {
                    int dc = h * HDIM + t * 8 + 2 * lr;
                    if (r0 < NTOK)
                        *(uint2*)&qsu[r0 * QKV_STRIDE + dc] =
                            make_uint2(cvt_tf32(o[t][0] * inv2[0]),
                                       cvt_tf32(o[t][1] * inv2[0]));
                    if (r1 < NTOK)
                        *(uint2*)&qsu[r1 * QKV_STRIDE + dc] =
                            make_uint2(cvt_tf32(o[t][2] * inv2[1]),
                                       cvt_tf32(o[t][3] * inv2[1]));
                }
            }
        }
        __syncthreads();

        // ====== phase 3: out = O @ w_proj + b_proj (TF32 MMA, B from L2) ======
        {
            const int ns = w >> 1;
            const int m0 = (w & 1) * 32;
            const uint2* gw = g_wfrag3 + ns * 2304 + lane;

            float d[2][3][4];
            #pragma unroll
            for (int s = 0; s < 2; s++)
                #pragma unroll
                for (int t = 0; t < 3; t++)
                    #pragma unroll
                    for (int j = 0; j < 4; j++) d[s][t][j] = 0.0f;

            const unsigned oab = sbase +
                ((OFF_QS + (m0 + lrow) * QKV_STRIDE + lcol) << 2);
            #pragma unroll 4
            for (int k8 = 0; k8 < 24; ++k8) {
                uint2 bbv[3];
                #pragma unroll
                for (int t = 0; t < 3; t++) bbv[t] = gw[(k8 * 3 + t) * 32];

                unsigned a[2][4];
                ldsm4(a[0], oab + (k8 * 8 << 2));
                ldsm4(a[1], oab + ((16 * QKV_STRIDE + k8 * 8) << 2));
                #pragma unroll
                for (int t = 0; t < 3; t++) {
                    mma_tf32(d[0][t], a[0], (const unsigned*)&bbv[t]);
                    mma_tf32(d[1][t], a[1], (const unsigned*)&bbv[t]);
                }
            }
            float* og = out + (size_t)b * (NTOK * DIMC);
            #pragma unroll
            for (int s = 0; s < 2; s++) {
                int r0 = m0 + s * 16 + lg, r1 = r0 + 8;
                #pragma unroll
                for (int t = 0; t < 3; t++) {
                    int col = ns * 24 + t * 8 + 2 * lr;
                    float2 bv = *(const float2*)&b_proj[col];
                    if (r0 < NTOK)
                        *(float2*)&og[r0 * DIMC + col] =
                            make_float2(d[s][t][0] + bv.x, d[s][t][1] + bv.y);
                    if (r1 < NTOK)
                        *(float2*)&og[r1 * DIMC + col] =
                            make_float2(d[s][t][2] + bv.x, d[s][t][3] + bv.y);
                }
            }
        }
        __syncthreads();   // qsu (O) reads done before next window's copy-in
    }
}

extern "C" void kernel_launch(void* const* d_in, const int* in_sizes, int n_in,
                              void* d_out, int out_size)
{
    const float* x      = (const float*)d_in[0];
    const float* mask   = (const float*)d_in[1];
    const float* w_qkv  = (const float*)d_in[2];
    const float* b_qkv  = (const float*)d_in[3];
    const float* w_proj = (const float*)d_in[4];
    const float* b_proj = (const float*)d_in[5];
    const float* table  = (const float*)d_in[6];
    float* out = (float*)d_out;

    prep_kernel<<<148, 256>>>(w_qkv, w_proj, table, mask, b_qkv);

    const int gsmem = GSMEM_WORDS * (int)sizeof(unsigned);
    cudaFuncSetAttribute(qkv_gemm_kernel,
                         cudaFuncAttributeMaxDynamicSharedMemorySize, gsmem);
    qkv_gemm_kernel<<<GROWS / 128, NTHREADS, gsmem>>>(x);

    const int smem_bytes = SMEM_WORDS * (int)sizeof(unsigned);
    cudaFuncSetAttribute(winattn_kernel,
                         cudaFuncAttributeMaxDynamicSharedMemorySize, smem_bytes);
    winattn_kernel<<<NCTAS, NTHREADS, smem_bytes>>>(b_proj, out);
}

// round 12
// speedup vs baseline: 1.5584x; 1.5584x over previous
#include <cuda_runtime.h>
#include <math.h>

#define NTOK   49
#define DIMC   192
#define HEADS  6
#define HDIM   32
#define NWMASK 64
#define QSCALE 0.17677669529663687f
#define LOG2E  1.4426950408889634f
#define NTHREADS 512
#define NCTAS   1024
#define WPC     4

#define XS_STRIDE  196
#define QKV_STRIDE 196
#define VT_STRIDE  60
#define ATT_STRIDE 60

#define OFF_QS 17640
#define OFF_KS 27244
#define OFF_VT 36848
#define SMEM_WORDS (36848 + 192 * 60)      // 48368 words = 193,472 B

__device__ uint2 g_wfrag1[8 * 24 * 9 * 32];        // q-cols pre-scaled by QSCALE*LOG2E
__device__ uint2 g_wfrag3[8 * 24 * 3 * 32];
__device__ float g_bq[576];                         // bias, q-part pre-scaled
__device__ float g_cmb[NWMASK * HEADS * NTOK * 56]; // (bias+mask)*LOG2E
__device__ float g_bp2[DIMC];                       // b_proj copy (float2-aligned reads)

__device__ __forceinline__ unsigned cvt_tf32(float f) {
    unsigned r;
    asm("cvt.rna.tf32.f32 %0, %1;" : "=r"(r) : "f"(f));
    return r;
}

__device__ __forceinline__ void mma_tf32(float* d, const unsigned* a, const unsigned* bb) {
    asm volatile(
        "mma.sync.aligned.m16n8k8.row.col.f32.tf32.tf32.f32 "
        "{%0,%1,%2,%3}, {%4,%5,%6,%7}, {%8,%9}, {%0,%1,%2,%3};"
        : "+f"(d[0]), "+f"(d[1]), "+f"(d[2]), "+f"(d[3])
        : "r"(a[0]), "r"(a[1]), "r"(a[2]), "r"(a[3]),
          "r"(bb[0]), "r"(bb[1]));
}

__device__ __forceinline__ void ldsm4(unsigned* r, unsigned addr) {
    asm volatile("ldmatrix.sync.aligned.m8n8.x4.shared.b16 {%0,%1,%2,%3}, [%4];"
                 : "=r"(r[0]), "=r"(r[1]), "=r"(r[2]), "=r"(r[3]) : "r"(addr));
}

__device__ __forceinline__ void ldsm2(unsigned* r, unsigned addr) {
    asm volatile("ldmatrix.sync.aligned.m8n8.x2.shared.b16 {%0,%1}, [%2];"
                 : "=r"(r[0]), "=r"(r[1]) : "r"(addr));
}

__global__ void prep_kernel(const float* __restrict__ w_qkv,
                            const float* __restrict__ w_proj,
                            const float* __restrict__ table,
                            const float* __restrict__ mask,
                            const float* __restrict__ b_qkv,
                            const float* __restrict__ b_proj)
{
    const int stride = gridDim.x * blockDim.x;
    const int tid0 = blockIdx.x * blockDim.x + threadIdx.x;

    for (int i = tid0; i < 8 * 24 * 9 * 32; i += stride) {
        int lane = i & 31;
        int t    = (i >> 5) % 9;
        int k8   = (i / 288) % 24;
        int ns   = i / 6912;
        int lr = lane & 3, lg = lane >> 2;
        int col = ns * 72 + t * 8 + lg;
        int k0  = k8 * 8 + lr;
        float sc = (col < DIMC) ? (QSCALE * LOG2E) : 1.0f;
        g_wfrag1[i] = make_uint2(cvt_tf32(w_qkv[k0 * 576 + col] * sc),
                                 cvt_tf32(w_qkv[(k0 + 4) * 576 + col] * sc));
    }
    for (int i = tid0; i < 8 * 24 * 3 * 32; i += stride) {
        int lane = i & 31;
        int t    = (i >> 5) % 3;
        int k8   = (i / 96) % 24;
        int ns   = i / 2304;
        int lr = lane & 3, lg = lane >> 2;
        int col = ns * 24 + t * 8 + lg;
        int k0  = k8 * 8 + lr;
        g_wfrag3[i] = make_uint2(cvt_tf32(w_proj[k0 * 192 + col]),
                                 cvt_tf32(w_proj[(k0 + 4) * 192 + col]));
    }
    for (int i = tid0; i < 576; i += stride)
        g_bq[i] = b_qkv[i] * (i < DIMC ? (QSCALE * LOG2E) : 1.0f);
    for (int i = tid0; i < DIMC; i += stride)
        g_bp2[i] = b_proj[i];

    for (int i = tid0; i < NWMASK * HEADS * NTOK * NTOK; i += stride) {
        int wm = i / (HEADS * NTOK * NTOK);
        int r  = i % (HEADS * NTOK * NTOK);
        int h  = r / (NTOK * NTOK);
        int r2 = r % (NTOK * NTOK);
        int p = r2 / NTOK, q = r2 % NTOK;
        int ip = p / 7, jp = p % 7, iq = q / 7, jq = q % 7;
        int ridx = (jp - jq + 6) * 13 + (ip - iq + 6);
        g_cmb[((wm * HEADS + h) * NTOK + p) * 56 + q] =
            (mask[wm * (NTOK * NTOK) + p * NTOK + q] + table[ridx * HEADS + h]) * LOG2E;
    }
}

__global__ __launch_bounds__(NTHREADS, 1)
void winattn_fused_kernel(const float* __restrict__ x,
                          float* __restrict__ out)
{
    extern __shared__ unsigned smu[];

    unsigned* xsu  = smu;
    unsigned* attu = smu;
    unsigned* qsu  = smu + OFF_QS;
    unsigned* ksu  = smu + OFF_KS;
    unsigned* vtu  = smu + OFF_VT;

    const unsigned sbase = (unsigned)__cvta_generic_to_shared(smu);

    const int tid  = threadIdx.x;
    const int lane = tid & 31;
    const int w    = tid >> 5;
    const int lg   = lane >> 2;
    const int lr   = lane & 3;
    const int lrow = (lane & 7) + ((lane >> 3) & 1) * 8;   // A-ldsm row
    const int lcol = (lane >> 4) * 4;                      // A-ldsm col
    const int brow8 = lane & 7;                            // B-ldsm row-within-tile
    const int bcol  = ((lane >> 3) & 1) * 4;               // B-ldsm col (0 or 4)
    const int btsel = lane >> 4;                           // B-ldsm tile select

    {
        const float4* xg4 = (const float4*)(x + (size_t)blockIdx.x * WPC * (NTOK * DIMC));
        #pragma unroll
        for (int j = 0; j < 5; j++) {
            int idx = tid + j * NTHREADS;
            if (idx < 2352) {
                float4 v = xg4[idx];
                int row = idx / 48, c4 = idx % 48;
                *(uint4*)&xsu[row * XS_STRIDE + c4 * 4] =
                    make_uint4(cvt_tf32(v.x), cvt_tf32(v.y), cvt_tf32(v.z), cvt_tf32(v.w));
            }
        }
        for (int i = tid; i < DIMC * 7; i += NTHREADS)
            vtu[(i / 7) * VT_STRIDE + 49 + (i % 7)] = 0u;   // pad persists all windows
    }
    __syncthreads();

    for (int it = 0; it < WPC; ++it) {
        const int b = blockIdx.x * WPC + it;

        // ====== phase 1: qkv = x @ w_qkv + b (TF32 MMA, B from L2) ======
        {
            const int ns = w >> 1;
            const int m0 = (w & 1) * 32;
            const uint2* gw = g_wfrag1 + ns * 6912 + lane;

            float d[2][9][4];
            #pragma unroll
            for (int s = 0; s < 2; s++)
                #pragma unroll
                for (int t = 0; t < 9; t++)
                    #pragma unroll
                    for (int j = 0; j < 4; j++) d[s][t][j] = 0.0f;

            const unsigned abase = sbase + (((m0 + lrow) * XS_STRIDE + lcol) << 2);
            #pragma unroll 4
            for (int k8 = 0; k8 < 24; ++k8) {
                uint2 bbv[9];
                #pragma unroll
                for (int t = 0; t < 9; t++) bbv[t] = gw[(k8 * 9 + t) * 32];

                unsigned a[2][4];
                ldsm4(a[0], abase + (k8 * 8 << 2));
                ldsm4(a[1], abase + ((16 * XS_STRIDE + k8 * 8) << 2));
                #pragma unroll
                for (int t = 0; t < 9; t++) {
                    mma_tf32(d[0][t], a[0], (const unsigned*)&bbv[t]);
                    mma_tf32(d[1][t], a[1], (const unsigned*)&bbv[t]);
                }
            }
            #pragma unroll
            for (int s = 0; s < 2; s++) {
                int r0 = m0 + s * 16 + lg, r1 = r0 + 8;
                #pragma unroll
                for (int t = 0; t < 9; t++) {
                    int col  = ns * 72 + t * 8 + 2 * lr;
                    int part = col / DIMC;
                    int cc   = col % DIMC;
                    float2 bq = *(const float2*)&g_bq[col];
                    if (part == 0) {
                        if (r0 < NTOK)
                            *(uint2*)&qsu[r0 * QKV_STRIDE + cc] =
                                make_uint2(cvt_tf32(d[s][t][0] + bq.x),
                                           cvt_tf32(d[s][t][1] + bq.y));
                        if (r1 < NTOK)
                            *(uint2*)&qsu[r1 * QKV_STRIDE + cc] =
                                make_uint2(cvt_tf32(d[s][t][2] + bq.x),
                                           cvt_tf32(d[s][t][3] + bq.y));
                    } else if (part == 1) {
                        if (r0 < NTOK)
                            *(uint2*)&ksu[r0 * QKV_STRIDE + cc] =
                                make_uint2(cvt_tf32(d[s][t][0] + bq.x),
                                           cvt_tf32(d[s][t][1] + bq.y));
                        if (r1 < NTOK)
                            *(uint2*)&ksu[r1 * QKV_STRIDE + cc] =
                                make_uint2(cvt_tf32(d[s][t][2] + bq.x),
                                           cvt_tf32(d[s][t][3] + bq.y));
                    } else {
                        if (r0 < NTOK) {
                            vtu[cc * VT_STRIDE + r0]       = cvt_tf32(d[s][t][0] + bq.x);
                            vtu[(cc + 1) * VT_STRIDE + r0] = cvt_tf32(d[s][t][1] + bq.y);
                        }
                        if (r1 < NTOK) {
                            vtu[cc * VT_STRIDE + r1]       = cvt_tf32(d[s][t][2] + bq.x);
                            vtu[(cc + 1) * VT_STRIDE + r1] = cvt_tf32(d[s][t][3] + bq.y);
                        }
                    }
                }
            }
        }
        __syncthreads();

        // ====== phase 2: attention — 24 (head, m16-tile) units over 16 warps ======
        {
            const int wm = b & (NWMASK - 1);
            for (int ui = w; ui < 24; ui += 16) {
                const int h  = ui >> 2;
                const int m0 = (ui & 3) * 16;

                float2 cmb[2][7];
                #pragma unroll
                for (int half = 0; half < 2; half++) {
                    int p = m0 + lg + 8 * half;
                    int pc = (p < NTOK) ? p : (NTOK - 1);
                    const float2* crow =
                        (const float2*)&g_cmb[((wm * HEADS + h) * NTOK + pc) * 56];
                    #pragma unroll
                    for (int t = 0; t < 7; t++)
                        cmb[half][t] = crow[(t * 8 + 2 * lr) >> 1];
                }

                float d[7][4];
                #pragma unroll
                for (int t = 0; t < 7; t++)
                    #pragma unroll
                    for (int j = 0; j < 4; j++) d[t][j] = 0.0f;

                const unsigned qab = sbase +
                    ((OFF_QS + (m0 + lrow) * QKV_STRIDE + h * HDIM + lcol) << 2);
                const unsigned kB0 = sbase +
                    ((OFF_KS + (btsel * 8 + brow8) * QKV_STRIDE + h * HDIM + bcol) << 2);
                #pragma unroll
                for (int k8 = 0; k8 < 4; ++k8) {
                    unsigned a[4];
                    ldsm4(a, qab + (k8 * 8 << 2));
                    unsigned bb[14];
                    ldsm4(bb,      kB0 + ((0 * 8 * QKV_STRIDE + k8 * 8) << 2));
                    ldsm4(bb + 4,  kB0 + ((2 * 8 * QKV_STRIDE + k8 * 8) << 2));
                    ldsm4(bb + 8,  kB0 + ((4 * 8 * QKV_STRIDE + k8 * 8) << 2));
                    ldsm2(bb + 12, kB0 + ((6 * 8 * QKV_STRIDE + k8 * 8) << 2));
                    #pragma unroll
                    for (int t = 0; t < 7; t++)
                        mma_tf32(d[t], a, bb + 2 * t);
                }

                // softmax in base-2 domain (scales folded in prep); deferred norm
                float inv2[2];
                #pragma unroll
                for (int half = 0; half < 2; half++) {
                    int p = m0 + lg + 8 * half;
                    float mx = -1e30f;
                    if (p < NTOK) {
                        #pragma unroll
                        for (int t = 0; t < 7; t++) {
                            int q0 = t * 8 + 2 * lr;
                            float v0 = -1e30f, v1 = -1e30f;
                            if (q0 < NTOK)     v0 = d[t][2 * half]     + cmb[half][t].x;
                            if (q0 + 1 < NTOK) v1 = d[t][2 * half + 1] + cmb[half][t].y;
                            d[t][2 * half]     = v0;
                            d[t][2 * half + 1] = v1;
                            mx = fmaxf(mx, fmaxf(v0, v1));
                        }
                    }
                    mx = fmaxf(mx, __shfl_xor_sync(0xffffffffu, mx, 1));
                    mx = fmaxf(mx, __shfl_xor_sync(0xffffffffu, mx, 2));
                    float sum = 0.0f;
                    if (p < NTOK) {
                        #pragma unroll
                        for (int t = 0; t < 7; t++) {
                            #pragma unroll
                            for (int c = 0; c < 2; c++) {
                                int q = t * 8 + 2 * lr + c;
                                float e = (q < NTOK) ? exp2f(d[t][2 * half + c] - mx) : 0.0f;
                                d[t][2 * half + c] = e;
                                sum += e;
                            }
                        }
                        unsigned* arow = attu + (h * NTOK + p) * ATT_STRIDE;
                        #pragma unroll
                        for (int t = 0; t < 7; t++) {
                            int q0 = t * 8 + 2 * lr;
                            uint2 bits = make_uint2(0u, 0u);
                            if (q0 < NTOK)     bits.x = cvt_tf32(d[t][2 * half]);
                            if (q0 + 1 < NTOK) bits.y = cvt_tf32(d[t][2 * half + 1]);
                            *(uint2*)&arow[q0] = bits;
                        }
                    }
                    sum += __shfl_xor_sync(0xffffffffu, sum, 1);
                    sum += __shfl_xor_sync(0xffffffffu, sum, 2);
                    inv2[half] = 1.0f / sum;
                }
                __syncwarp();

                float o[4][4];
                #pragma unroll
                for (int t = 0; t < 4; t++)
                    #pragma unroll
                    for (int j = 0; j < 4; j++) o[t][j] = 0.0f;

                const unsigned aab = sbase +
                    (((h * NTOK + m0 + lrow) * ATT_STRIDE + lcol) << 2);
                const unsigned vB0 = sbase +
                    ((OFF_VT + (h * HDIM + btsel * 8 + brow8) * VT_STRIDE + bcol) << 2);
                #pragma unroll
                for (int k8 = 0; k8 < 7; ++k8) {
                    unsigned a[4];
                    ldsm4(a, aab + (k8 * 8 << 2));
                    unsigned bb[8];
                    ldsm4(bb,     vB0 + ((0 * 8 * VT_STRIDE + k8 * 8) << 2));
                    ldsm4(bb + 4, vB0 + ((2 * 8 * VT_STRIDE + k8 * 8) << 2));
                    #pragma unroll
                    for (int t = 0; t < 4; t++)
                        mma_tf32(o[t], a, bb + 2 * t);
                }
                int r0 = m0 + lg, r1 = r0 + 8;
                #pragma unroll
                for (int t = 0; t < 4; t++) {
                    int dc = h * HDIM + t * 8 + 2 * lr;
                    if (r0 < NTOK)
                        *(uint2*)&qsu[r0 * QKV_STRIDE + dc] =
                            make_uint2(cvt_tf32(o[t][0] * inv2[0]),
                                       cvt_tf32(o[t][1] * inv2[0]));
                    if (r1 < NTOK)
                        *(uint2*)&qsu[r1 * QKV_STRIDE + dc] =
                            make_uint2(cvt_tf32(o[t][2] * inv2[1]),
                                       cvt_tf32(o[t][3] * inv2[1]));
                }
            }
        }
        __syncthreads();

        const bool havex = (it + 1 < WPC);
        float4 xpre[5];
        if (havex) {
            const float4* xg4 = (const float4*)(x + (size_t)(b + 1) * (NTOK * DIMC));
            #pragma unroll
            for (int j = 0; j < 5; j++) {
                int idx = tid + j * NTHREADS;
                if (idx < 2352) xpre[j] = xg4[idx];
            }
        }

        // ====== phase 3: out = O @ w_proj + b_proj (TF32 MMA, B from L2) ======
        {
            const int ns = w >> 1;
            const int m0 = (w & 1) * 32;
            const uint2* gw = g_wfrag3 + ns * 2304 + lane;

            float d[2][3][4];
            #pragma unroll
            for (int s = 0; s < 2; s++)
                #pragma unroll
                for (int t = 0; t < 3; t++)
                    #pragma unroll
                    for (int j = 0; j < 4; j++) d[s][t][j] = 0.0f;

            const unsigned oab = sbase +
                ((OFF_QS + (m0 + lrow) * QKV_STRIDE + lcol) << 2);
            #pragma unroll 4
            for (int k8 = 0; k8 < 24; ++k8) {
                uint2 bbv[3];
                #pragma unroll
                for (int t = 0; t < 3; t++) bbv[t] = gw[(k8 * 3 + t) * 32];

                unsigned a[2][4];
                ldsm4(a[0], oab + (k8 * 8 << 2));
                ldsm4(a[1], oab + ((16 * QKV_STRIDE + k8 * 8) << 2));
                #pragma unroll
                for (int t = 0; t < 3; t++) {
                    mma_tf32(d[0][t], a[0], (const unsigned*)&bbv[t]);
                    mma_tf32(d[1][t], a[1], (const unsigned*)&bbv[t]);
                }
            }
            float* og = out + (size_t)b * (NTOK * DIMC);
            #pragma unroll
            for (int s = 0; s < 2; s++) {
                int r0 = m0 + s * 16 + lg, r1 = r0 + 8;
                #pragma unroll
                for (int t = 0; t < 3; t++) {
                    int col = ns * 24 + t * 8 + 2 * lr;
                    float2 bv = *(const float2*)&g_bp2[col];
                    if (r0 < NTOK)
                        *(float2*)&og[r0 * DIMC + col] =
                            make_float2(d[s][t][0] + bv.x, d[s][t][1] + bv.y);
                    if (r1 < NTOK)
                        *(float2*)&og[r1 * DIMC + col] =
                            make_float2(d[s][t][2] + bv.x, d[s][t][3] + bv.y);
                }
            }
        }

        if (havex) {
            #pragma unroll
            for (int j = 0; j < 5; j++) {
                int idx = tid + j * NTHREADS;
                if (idx < 2352) {
                    int row = idx / 48, c4 = idx % 48;
                    *(uint4*)&xsu[row * XS_STRIDE + c4 * 4] =
                        make_uint4(cvt_tf32(xpre[j].x), cvt_tf32(xpre[j].y),
                                   cvt_tf32(xpre[j].z), cvt_tf32(xpre[j].w));
                }
            }
        }
        __syncthreads();
    }
}

extern "C" void kernel_launch(void* const* d_in, const int* in_sizes, int n_in,
                              void* d_out, int out_size)
{
    const float* x      = (const float*)d_in[0];
    const float* mask   = (const float*)d_in[1];
    const float* w_qkv  = (const float*)d_in[2];
    const float* b_qkv  = (const float*)d_in[3];
    const float* w_proj = (const float*)d_in[4];
    const float* b_proj = (const float*)d_in[5];
    const float* table  = (const float*)d_in[6];
    float* out = (float*)d_out;

    prep_kernel<<<148, 256>>>(w_qkv, w_proj, table, mask, b_qkv, b_proj);

    const int smem_bytes = SMEM_WORDS * (int)sizeof(unsigned);
    cudaFuncSetAttribute(winattn_fused_kernel,
                         cudaFuncAttributeMaxDynamicSharedMemorySize, smem_bytes);

    winattn_fused_kernel<<<NCTAS, NTHREADS, smem_bytes>>>(x, out);
}

// round 13
// speedup vs baseline: 1.7648x; 1.1324x over previous
#include <cuda_runtime.h>
#include <math.h>

#define NTOK   49
#define DIMC   192
#define HEADS  6
#define HDIM   32
#define NWMASK 64
#define QSCALE 0.17677669529663687f
#define LOG2E  1.4426950408889634f
#define NTHREADS 768
#define NCTAS   1024
#define WPC     4

#define XS_STRIDE  196
#define QKV_STRIDE 196
#define VT_STRIDE  60
#define ATT_STRIDE 60

#define OFF_QS 17640
#define OFF_KS 27244
#define OFF_VT 36848
#define SMEM_WORDS (36848 + 192 * 60)      // 48368 words = 193,472 B

// 12 N-slices of 48 cols (phase 1) / 16 cols (phase 3)
__device__ uint2 g_wfrag1[12 * 24 * 6 * 32];       // q-cols pre-scaled by QSCALE*LOG2E
__device__ uint2 g_wfrag3[12 * 24 * 2 * 32];
__device__ float g_bq[576];                         // bias, q-part pre-scaled
__device__ float g_cmb[NWMASK * HEADS * NTOK * 56]; // (bias+mask)*LOG2E
__device__ float g_bp2[DIMC];

__device__ __forceinline__ unsigned cvt_tf32(float f) {
    unsigned r;
    asm("cvt.rna.tf32.f32 %0, %1;" : "=r"(r) : "f"(f));
    return r;
}

__device__ __forceinline__ void mma_tf32(float* d, const unsigned* a, const unsigned* bb) {
    asm volatile(
        "mma.sync.aligned.m16n8k8.row.col.f32.tf32.tf32.f32 "
        "{%0,%1,%2,%3}, {%4,%5,%6,%7}, {%8,%9}, {%0,%1,%2,%3};"
        : "+f"(d[0]), "+f"(d[1]), "+f"(d[2]), "+f"(d[3])
        : "r"(a[0]), "r"(a[1]), "r"(a[2]), "r"(a[3]),
          "r"(bb[0]), "r"(bb[1]));
}

__device__ __forceinline__ void ldsm4(unsigned* r, unsigned addr) {
    asm volatile("ldmatrix.sync.aligned.m8n8.x4.shared.b16 {%0,%1,%2,%3}, [%4];"
                 : "=r"(r[0]), "=r"(r[1]), "=r"(r[2]), "=r"(r[3]) : "r"(addr));
}

__device__ __forceinline__ void ldsm2(unsigned* r, unsigned addr) {
    asm volatile("ldmatrix.sync.aligned.m8n8.x2.shared.b16 {%0,%1}, [%2];"
                 : "=r"(r[0]), "=r"(r[1]) : "r"(addr));
}

__global__ void prep_kernel(const float* __restrict__ w_qkv,
                            const float* __restrict__ w_proj,
                            const float* __restrict__ table,
                            const float* __restrict__ mask,
                            const float* __restrict__ b_qkv,
                            const float* __restrict__ b_proj)
{
    const int stride = gridDim.x * blockDim.x;
    const int tid0 = blockIdx.x * blockDim.x + threadIdx.x;

    for (int i = tid0; i < 12 * 24 * 6 * 32; i += stride) {
        int lane = i & 31;
        int t    = (i >> 5) % 6;
        int k8   = (i / 192) % 24;
        int ns   = i / 4608;
        int lr = lane & 3, lg = lane >> 2;
        int col = ns * 48 + t * 8 + lg;
        int k0  = k8 * 8 + lr;
        float sc = (col < DIMC) ? (QSCALE * LOG2E) : 1.0f;
        g_wfrag1[i] = make_uint2(cvt_tf32(w_qkv[k0 * 576 + col] * sc),
                                 cvt_tf32(w_qkv[(k0 + 4) * 576 + col] * sc));
    }
    for (int i = tid0; i < 12 * 24 * 2 * 32; i += stride) {
        int lane = i & 31;
        int t    = (i >> 5) % 2;
        int k8   = (i / 64) % 24;
        int ns   = i / 1536;
        int lr = lane & 3, lg = lane >> 2;
        int col = ns * 16 + t * 8 + lg;
        int k0  = k8 * 8 + lr;
        g_wfrag3[i] = make_uint2(cvt_tf32(w_proj[k0 * 192 + col]),
                                 cvt_tf32(w_proj[(k0 + 4) * 192 + col]));
    }
    for (int i = tid0; i < 576; i += stride)
        g_bq[i] = b_qkv[i] * (i < DIMC ? (QSCALE * LOG2E) : 1.0f);
    for (int i = tid0; i < DIMC; i += stride)
        g_bp2[i] = b_proj[i];

    for (int i = tid0; i < NWMASK * HEADS * NTOK * NTOK; i += stride) {
        int wm = i / (HEADS * NTOK * NTOK);
        int r  = i % (HEADS * NTOK * NTOK);
        int h  = r / (NTOK * NTOK);
        int r2 = r % (NTOK * NTOK);
        int p = r2 / NTOK, q = r2 % NTOK;
        int ip = p / 7, jp = p % 7, iq = q / 7, jq = q % 7;
        int ridx = (jp - jq + 6) * 13 + (ip - iq + 6);
        g_cmb[((wm * HEADS + h) * NTOK + p) * 56 + q] =
            (mask[wm * (NTOK * NTOK) + p * NTOK + q] + table[ridx * HEADS + h]) * LOG2E;
    }
}

__global__ __launch_bounds__(NTHREADS, 1)
void winattn_fused_kernel(const float* __restrict__ x,
                          float* __restrict__ out)
{
    extern __shared__ unsigned smu[];

    unsigned* xsu  = smu;
    unsigned* attu = smu;
    unsigned* qsu  = smu + OFF_QS;
    unsigned* ksu  = smu + OFF_KS;
    unsigned* vtu  = smu + OFF_VT;

    const unsigned sbase = (unsigned)__cvta_generic_to_shared(smu);

    const int tid  = threadIdx.x;
    const int lane = tid & 31;
    const int w    = tid >> 5;                             // 0..23
    const int lg   = lane >> 2;
    const int lr   = lane & 3;
    const int lrow = (lane & 7) + ((lane >> 3) & 1) * 8;   // A-ldsm row
    const int lcol = (lane >> 4) * 4;                      // A-ldsm col
    const int brow8 = lane & 7;                            // B-ldsm row-within-tile
    const int bcol  = ((lane >> 3) & 1) * 4;               // B-ldsm col (0 or 4)
    const int btsel = lane >> 4;                           // B-ldsm tile select

    {
        const float4* xg4 = (const float4*)(x + (size_t)blockIdx.x * WPC * (NTOK * DIMC));
        #pragma unroll
        for (int j = 0; j < 4; j++) {
            int idx = tid + j * NTHREADS;
            if (idx < 2352) {
                float4 v = xg4[idx];
                int row = idx / 48, c4 = idx % 48;
                *(uint4*)&xsu[row * XS_STRIDE + c4 * 4] =
                    make_uint4(cvt_tf32(v.x), cvt_tf32(v.y), cvt_tf32(v.z), cvt_tf32(v.w));
            }
        }
        for (int i = tid; i < DIMC * 7; i += NTHREADS)
            vtu[(i / 7) * VT_STRIDE + 49 + (i % 7)] = 0u;   // pad persists all windows
    }
    __syncthreads();

    for (int it = 0; it < WPC; ++it) {
        const int b = blockIdx.x * WPC + it;

        // ====== phase 1: qkv = x @ w_qkv + b (TF32 MMA, B from L2) ======
        // warp = (ns 0..11 of 48 cols, m-half 0..1 of 32 rows)
        {
            const int ns = w >> 1;
            const int m0 = (w & 1) * 32;
            const int part = ns >> 2;                       // 0=q 1=k 2=v (warp-constant)
            const uint2* gw = g_wfrag1 + ns * 4608 + lane;

            float d[2][6][4];
            #pragma unroll
            for (int s = 0; s < 2; s++)
                #pragma unroll
                for (int t = 0; t < 6; t++)
                    #pragma unroll
                    for (int j = 0; j < 4; j++) d[s][t][j] = 0.0f;

            const unsigned abase = sbase + (((m0 + lrow) * XS_STRIDE + lcol) << 2);
            #pragma unroll 4
            for (int k8 = 0; k8 < 24; ++k8) {
                uint2 bbv[6];
                #pragma unroll
                for (int t = 0; t < 6; t++) bbv[t] = gw[(k8 * 6 + t) * 32];

                unsigned a[2][4];
                ldsm4(a[0], abase + (k8 * 8 << 2));
                ldsm4(a[1], abase + ((16 * XS_STRIDE + k8 * 8) << 2));
                #pragma unroll
                for (int t = 0; t < 6; t++) {
                    mma_tf32(d[0][t], a[0], (const unsigned*)&bbv[t]);
                    mma_tf32(d[1][t], a[1], (const unsigned*)&bbv[t]);
                }
            }
            // epilogue: +bias; warp-constant destination
            unsigned* dst = (part == 0) ? qsu : (part == 1) ? ksu : vtu;
            #pragma unroll
            for (int s = 0; s < 2; s++) {
                int r0 = m0 + s * 16 + lg, r1 = r0 + 8;
                #pragma unroll
                for (int t = 0; t < 6; t++) {
                    int col = ns * 48 + t * 8 + 2 * lr;
                    int cc  = (ns & 3) * 48 + t * 8 + 2 * lr;
                    float2 bq = *(const float2*)&g_bq[col];
                    if (part < 2) {
                        if (r0 < NTOK)
                            *(uint2*)&dst[r0 * QKV_STRIDE + cc] =
                                make_uint2(cvt_tf32(d[s][t][0] + bq.x),
                                           cvt_tf32(d[s][t][1] + bq.y));
                        if (r1 < NTOK)
                            *(uint2*)&dst[r1 * QKV_STRIDE + cc] =
                                make_uint2(cvt_tf32(d[s][t][2] + bq.x),
                                           cvt_tf32(d[s][t][3] + bq.y));
                    } else {
                        if (r0 < NTOK) {
                            dst[cc * VT_STRIDE + r0]       = cvt_tf32(d[s][t][0] + bq.x);
                            dst[(cc + 1) * VT_STRIDE + r0] = cvt_tf32(d[s][t][1] + bq.y);
                        }
                        if (r1 < NTOK) {
                            dst[cc * VT_STRIDE + r1]       = cvt_tf32(d[s][t][2] + bq.x);
                            dst[(cc + 1) * VT_STRIDE + r1] = cvt_tf32(d[s][t][3] + bq.y);
                        }
                    }
                }
            }
        }
        __syncthreads();

        // ====== phase 2: attention — 24 units, exactly 1 per warp ======
        {
            const int wm = b & (NWMASK - 1);
            const int h  = w >> 2;
            const int m0 = (w & 3) * 16;

            float2 cmb[2][7];
            #pragma unroll
            for (int half = 0; half < 2; half++) {
                int p = m0 + lg + 8 * half;
                int pc = (p < NTOK) ? p : (NTOK - 1);
                const float2* crow =
                    (const float2*)&g_cmb[((wm * HEADS + h) * NTOK + pc) * 56];
                #pragma unroll
                for (int t = 0; t < 7; t++)
                    cmb[half][t] = crow[(t * 8 + 2 * lr) >> 1];
            }

            float d[7][4];
            #pragma unroll
            for (int t = 0; t < 7; t++)
                #pragma unroll
                for (int j = 0; j < 4; j++) d[t][j] = 0.0f;

            const unsigned qab = sbase +
                ((OFF_QS + (m0 + lrow) * QKV_STRIDE + h * HDIM + lcol) << 2);
            const unsigned kB0 = sbase +
                ((OFF_KS + (btsel * 8 + brow8) * QKV_STRIDE + h * HDIM + bcol) << 2);
            #pragma unroll
            for (int k8 = 0; k8 < 4; ++k8) {
                unsigned a[4];
                ldsm4(a, qab + (k8 * 8 << 2));
                unsigned bb[14];
                ldsm4(bb,      kB0 + ((0 * 8 * QKV_STRIDE + k8 * 8) << 2));
                ldsm4(bb + 4,  kB0 + ((2 * 8 * QKV_STRIDE + k8 * 8) << 2));
                ldsm4(bb + 8,  kB0 + ((4 * 8 * QKV_STRIDE + k8 * 8) << 2));
                ldsm2(bb + 12, kB0 + ((6 * 8 * QKV_STRIDE + k8 * 8) << 2));
                #pragma unroll
                for (int t = 0; t < 7; t++)
                    mma_tf32(d[t], a, bb + 2 * t);
            }

            // softmax in base-2 domain; deferred normalization
            float inv2[2];
            #pragma unroll
            for (int half = 0; half < 2; half++) {
                int p = m0 + lg + 8 * half;
                float mx = -1e30f;
                if (p < NTOK) {
                    #pragma unroll
                    for (int t = 0; t < 7; t++) {
                        int q0 = t * 8 + 2 * lr;
                        float v0 = -1e30f, v1 = -1e30f;
                        if (q0 < NTOK)     v0 = d[t][2 * half]     + cmb[half][t].x;
                        if (q0 + 1 < NTOK) v1 = d[t][2 * half + 1] + cmb[half][t].y;
                        d[t][2 * half]     = v0;
                        d[t][2 * half + 1] = v1;
                        mx = fmaxf(mx, fmaxf(v0, v1));
                    }
                }
                mx = fmaxf(mx, __shfl_xor_sync(0xffffffffu, mx, 1));
                mx = fmaxf(mx, __shfl_xor_sync(0xffffffffu, mx, 2));
                float sum = 0.0f;
                if (p < NTOK) {
                    #pragma unroll
                    for (int t = 0; t < 7; t++) {
                        #pragma unroll
                        for (int c = 0; c < 2; c++) {
                            int q = t * 8 + 2 * lr + c;
                            float e = (q < NTOK) ? exp2f(d[t][2 * half + c] - mx) : 0.0f;
                            d[t][2 * half + c] = e;
                            sum += e;
                        }
                    }
                    unsigned* arow = attu + (h * NTOK + p) * ATT_STRIDE;
                    #pragma unroll
                    for (int t = 0; t < 7; t++) {
                        int q0 = t * 8 + 2 * lr;
                        uint2 bits = make_uint2(0u, 0u);
                        if (q0 < NTOK)     bits.x = cvt_tf32(d[t][2 * half]);
                        if (q0 + 1 < NTOK) bits.y = cvt_tf32(d[t][2 * half + 1]);
                        *(uint2*)&arow[q0] = bits;
                    }
                }
                sum += __shfl_xor_sync(0xffffffffu, sum, 1);
                sum += __shfl_xor_sync(0xffffffffu, sum, 2);
                inv2[half] = 1.0f / sum;
            }
            __syncwarp();

            float o[4][4];
            #pragma unroll
            for (int t = 0; t < 4; t++)
                #pragma unroll
                for (int j = 0; j < 4; j++) o[t][j] = 0.0f;

            const unsigned aab = sbase +
                (((h * NTOK + m0 + lrow) * ATT_STRIDE + lcol) << 2);
            const unsigned vB0 = sbase +
                ((OFF_VT + (h * HDIM + btsel * 8 + brow8) * VT_STRIDE + bcol) << 2);
            #pragma unroll
            for (int k8 = 0; k8 < 7; ++k8) {
                unsigned a[4];
                ldsm4(a, aab + (k8 * 8 << 2));
                unsigned bb[8];
                ldsm4(bb,     vB0 + ((0 * 8 * VT_STRIDE + k8 * 8) << 2));
                ldsm4(bb + 4, vB0 + ((2 * 8 * VT_STRIDE + k8 * 8) << 2));
                #pragma unroll
                for (int t = 0; t < 4; t++)
                    mma_tf32(o[t], a, bb + 2 * t);
            }
            int r0 = m0 + lg, r1 = r0 + 8;
            #pragma unroll
            for (int t = 0; t < 4; t++) {
                int dc = h * HDIM + t * 8 + 2 * lr;
                if (r0 < NTOK)
                    *(uint2*)&qsu[r0 * QKV_STRIDE + dc] =
                        make_uint2(cvt_tf32(o[t][0] * inv2[0]),
                                   cvt_tf32(o[t][1] * inv2[0]));
                if (r1 < NTOK)
                    *(uint2*)&qsu[r1 * QKV_STRIDE + dc] =
                        make_uint2(cvt_tf32(o[t][2] * inv2[1]),
                                   cvt_tf32(o[t][3] * inv2[1]));
            }
        }
        __syncthreads();

        const bool havex = (it + 1 < WPC);
        float4 xpre[4];
        if (havex) {
            const float4* xg4 = (const float4*)(x + (size_t)(b + 1) * (NTOK * DIMC));
            #pragma unroll
            for (int j = 0; j < 4; j++) {
                int idx = tid + j * NTHREADS;
                if (idx < 2352) xpre[j] = xg4[idx];
            }
        }

        // ====== phase 3: out = O @ w_proj + b_proj (TF32 MMA, B from L2) ======
        // warp = (ns 0..11 of 16 cols, m-half 0..1 of 32 rows)
        {
            const int ns = w >> 1;
            const int m0 = (w & 1) * 32;
            const uint2* gw = g_wfrag3 + ns * 1536 + lane;

            float d[2][2][4];
            #pragma unroll
            for (int s = 0; s < 2; s++)
                #pragma unroll
                for (int t = 0; t < 2; t++)
                    #pragma unroll
                    for (int j = 0; j < 4; j++) d[s][t][j] = 0.0f;

            const unsigned oab = sbase +
                ((OFF_QS + (m0 + lrow) * QKV_STRIDE + lcol) << 2);
            #pragma unroll 4
            for (int k8 = 0; k8 < 24; ++k8) {
                uint2 bbv[2];
                #pragma unroll
                for (int t = 0; t < 2; t++) bbv[t] = gw[(k8 * 2 + t) * 32];

                unsigned a[2][4];
                ldsm4(a[0], oab + (k8 * 8 << 2));
                ldsm4(a[1], oab + ((16 * QKV_STRIDE + k8 * 8) << 2));
                #pragma unroll
                for (int t = 0; t < 2; t++) {
                    mma_tf32(d[0][t], a[0], (const unsigned*)&bbv[t]);
                    mma_tf32(d[1][t], a[1], (const unsigned*)&bbv[t]);
                }
            }
            float* og = out + (size_t)b * (NTOK * DIMC);
            #pragma unroll
            for (int s = 0; s < 2; s++) {
                int r0 = m0 + s * 16 + lg, r1 = r0 + 8;
                #pragma unroll
                for (int t = 0; t < 2; t++) {
                    int col = ns * 16 + t * 8 + 2 * lr;
                    float2 bv = *(const float2*)&g_bp2[col];
                    if (r0 < NTOK)
                        *(float2*)&og[r0 * DIMC + col] =
                            make_float2(d[s][t][0] + bv.x, d[s][t][1] + bv.y);
                    if (r1 < NTOK)
                        *(float2*)&og[r1 * DIMC + col] =
                            make_float2(d[s][t][2] + bv.x, d[s][t][3] + bv.y);
                }
            }
        }

        if (havex) {
            #pragma unroll
            for (int j = 0; j < 4; j++) {
                int idx = tid + j * NTHREADS;
                if (idx < 2352) {
                    int row = idx / 48, c4 = idx % 48;
                    *(uint4*)&xsu[row * XS_STRIDE + c4 * 4] =
                        make_uint4(cvt_tf32(xpre[j].x), cvt_tf32(xpre[j].y),
                                   cvt_tf32(xpre[j].z), cvt_tf32(xpre[j].w));
                }
            }
        }
        __syncthreads();
    }
}

extern "C" void kernel_launch(void* const* d_in, const int* in_sizes, int n_in,
                              void* d_out, int out_size)
{
    const float* x      = (const float*)d_in[0];
    const float* mask   = (const float*)d_in[1];
    const float* w_qkv  = (const float*)d_in[2];
    const float* b_qkv  = (const float*)d_in[3];
    const float* w_proj = (const float*)d_in[4];
    const float* b_proj = (const float*)d_in[5];
    const float* table  = (const float*)d_in[6];
    float* out = (float*)d_out;

    prep_kernel<<<148, 256>>>(w_qkv, w_proj, table, mask, b_qkv, b_proj);

    const int smem_bytes = SMEM_WORDS * (int)sizeof(unsigned);
    cudaFuncSetAttribute(winattn_fused_kernel,
                         cudaFuncAttributeMaxDynamicSharedMemorySize, smem_bytes);

    winattn_fused_kernel<<<NCTAS, NTHREADS, smem_bytes>>>(x, out);
}